// round 10
// baseline (speedup 1.0000x reference)
#include <cuda_runtime.h>
#include <math.h>
#include <float.h>

#define NB     2
#define NSEQ   2048
#define DMODEL 1024
#define NH     16
#define DHD    64

// ---------------- scratch (device globals; no allocations allowed) ----------------
__device__ float g_xn  [NB * NSEQ * DMODEL];   // layernormed x
__device__ float g_q   [NB * NSEQ * DMODEL];   // q (scaled), layout [b*N + i][h*64 + d]
__device__ float g_kv  [NB * NSEQ * 2 * DHD];  // kv, layout [b*N + j][0:64 k | 64:128 v]
__device__ float g_ao  [NB * NSEQ * DMODEL];   // attention output, [b*N + i][h*64 + d]
__device__ float g_mask[NB * NSEQ];            // additive mask: 0 (keep) / -3e38 (drop)

// ---------------- packed f32x2 helpers (Blackwell FFMA2) ----------------
__device__ __forceinline__ unsigned long long dup2(float x) {
    unsigned long long r;
    unsigned int u = __float_as_uint(x);
    asm("mov.b64 %0, {%1, %2};" : "=l"(r) : "r"(u), "r"(u));
    return r;
}
__device__ __forceinline__ float2 unpk2(unsigned long long v) {
    unsigned int lo, hi;
    asm("mov.b64 {%0, %1}, %2;" : "=r"(lo), "=r"(hi) : "l"(v));
    return make_float2(__uint_as_float(lo), __uint_as_float(hi));
}
__device__ __forceinline__ void ffma2(unsigned long long& d, unsigned long long a, unsigned long long b) {
    asm("fma.rn.f32x2 %0, %1, %2, %0;" : "+l"(d) : "l"(a), "l"(b));
}
__device__ __forceinline__ void fmul2(unsigned long long& d, unsigned long long a) {
    asm("mul.rn.f32x2 %0, %0, %1;" : "+l"(d) : "l"(a));
}

// ---------------- layernorm (+ folded mask normalization on overflow blocks) ----------------
// Blocks [0, NB*NSEQ): one LN row each. Blocks >= NB*NSEQ: mask_norm stripes.
#define LN_ROWS (NB * NSEQ)
#define MASK_BLOCKS 8

__global__ __launch_bounds__(256) void ln_kernel(const float* __restrict__ x,
                                                 const float* __restrict__ w,
                                                 const float* __restrict__ bb,
                                                 float* __restrict__ xn,
                                                 const void* __restrict__ mraw,
                                                 float* __restrict__ mout) {
    int row = blockIdx.x;
    int t = threadIdx.x;
    if (row >= LN_ROWS) {
        // ---- mask path ----
        __shared__ int s_mode;
        if (t == 0) {
            const unsigned int* u = (const unsigned int*)mraw;
            bool isI = true, isF = true;
            for (int i = 0; i < 1024; i++) {       // first 4096 bytes, valid for any candidate dtype
                unsigned int v = u[i];
                if (v > 1u) isI = false;
                if (v != 0u && v != 0x3F800000u) isF = false;
            }
            s_mode = isI ? 1 : (isF ? 2 : 0);
        }
        __syncthreads();
        int mode = s_mode;
        int mb = row - LN_ROWS;
        for (int i = mb * 256 + t; i < LN_ROWS; i += MASK_BLOCKS * 256) {
            bool keep;
            if (mode == 1)      keep = (((const int*)mraw)[i]   != 0);
            else if (mode == 2) keep = (((const float*)mraw)[i] != 0.f);
            else                keep = (((const unsigned char*)mraw)[i] != 0);
            mout[i] = keep ? 0.f : -3.0e38f;
        }
        return;
    }
    const float4* xr = (const float4*)(x + (size_t)row * DMODEL);
    float4 v = xr[t];
    float s = v.x + v.y + v.z + v.w;
    float q = v.x * v.x + v.y * v.y + v.z * v.z + v.w * v.w;
#pragma unroll
    for (int o = 16; o > 0; o >>= 1) {
        s += __shfl_xor_sync(0xffffffffu, s, o);
        q += __shfl_xor_sync(0xffffffffu, q, o);
    }
    __shared__ float ss[8], sq[8];
    int wid = t >> 5, lid = t & 31;
    if (lid == 0) { ss[wid] = s; sq[wid] = q; }
    __syncthreads();
    s = 0.f; q = 0.f;
#pragma unroll
    for (int i = 0; i < 8; i++) { s += ss[i]; q += sq[i]; }
    float mu = s * (1.f / DMODEL);
    float var = q * (1.f / DMODEL) - mu * mu;
    float rstd = rsqrtf(var + 1e-5f);
    float4 wv = ((const float4*)w)[t];
    float4 bv = ((const float4*)bb)[t];
    float4 o;
    o.x = (v.x - mu) * rstd * wv.x + bv.x;
    o.y = (v.y - mu) * rstd * wv.y + bv.y;
    o.z = (v.z - mu) * rstd * wv.z + bv.z;
    o.w = (v.w - mu) * rstd * wv.w + bv.w;
    ((float4*)(xn + (size_t)row * DMODEL))[t] = o;
}

// ---------------- SGEMM 128x128: C = scale * (A[M,K] @ W[K,Nc]) ----------------
// Double-buffered smem, one __syncthreads per k-tile, 8x8 micro in packed f32x2.
// B pairs loaded directly as ulonglong2 (no pack MOVs on the LDS->FFMA2 path).
// __launch_bounds__(256, 2): cap regs at 128 so 2 CTAs/SM -> single-wave grids.
// Dual-operand form: blocks with blockIdx.x >= split use the secondary operand
// set (A2/W2/C2/Nc2/scale2, n-tile 0). Used to fold the narrow kv projection
// into the q-projection wave (288 CTAs <= 296 slots -> still one wave).
#define GBM 128
#define GBN 128
#define GBK 16
#define GPA 132

__global__ __launch_bounds__(256, 2) void sgemm_kernel(const float* __restrict__ Ap,
                                                       const float* __restrict__ Wp,
                                                       float* __restrict__ Cp,
                                                       int Ncp, int K, float scalep,
                                                       const float* __restrict__ A2,
                                                       const float* __restrict__ W2,
                                                       float* __restrict__ C2,
                                                       int Nc2, float scale2, int split) {
    __shared__ float As[2][GBK * GPA];
    __shared__ float Ws[2][GBK * GBN];
    int tid = threadIdx.x;
    int ti = tid >> 4, tj = tid & 15;

    const float* A; const float* W; float* C;
    int Nc; float scale; int n0;
    if ((int)blockIdx.x >= split) {
        A = A2; W = W2; C = C2; Nc = Nc2; scale = scale2; n0 = 0;
    } else {
        A = Ap; W = Wp; C = Cp; Nc = Ncp; scale = scalep; n0 = blockIdx.x * GBN;
    }
    int m0 = blockIdx.y * GBM;

    int am[2], ak4[2], wk[2], wn4[2];
#pragma unroll
    for (int p = 0; p < 2; p++) {
        int idx = tid + p * 256;
        am[p]  = idx >> 2;  ak4[p] = idx & 3;
        wk[p]  = idx >> 5;  wn4[p] = idx & 31;
    }

    unsigned long long acc[8][4];
#pragma unroll
    for (int i = 0; i < 8; i++)
#pragma unroll
        for (int j = 0; j < 4; j++) acc[i][j] = 0ull;

#pragma unroll
    for (int p = 0; p < 2; p++) {
        float4 av = *(const float4*)(A + (size_t)(m0 + am[p]) * K + ak4[p] * 4);
        As[0][(ak4[p] * 4 + 0) * GPA + am[p]] = av.x;
        As[0][(ak4[p] * 4 + 1) * GPA + am[p]] = av.y;
        As[0][(ak4[p] * 4 + 2) * GPA + am[p]] = av.z;
        As[0][(ak4[p] * 4 + 3) * GPA + am[p]] = av.w;
        float4 wv = *(const float4*)(W + (size_t)wk[p] * Nc + n0 + wn4[p] * 4);
        *(float4*)&Ws[0][wk[p] * GBN + wn4[p] * 4] = wv;
    }
    __syncthreads();

    int buf = 0;
    for (int kb = 0; kb < K; kb += GBK) {
        float4 an[2], wn[2];
        bool more = (kb + GBK) < K;
        if (more) {
#pragma unroll
            for (int p = 0; p < 2; p++) {
                an[p] = *(const float4*)(A + (size_t)(m0 + am[p]) * K + kb + GBK + ak4[p] * 4);
                wn[p] = *(const float4*)(W + (size_t)(kb + GBK + wk[p]) * Nc + n0 + wn4[p] * 4);
            }
        }
#pragma unroll
        for (int k = 0; k < GBK; k++) {
            float4 a0 = *(const float4*)&As[buf][k * GPA + ti * 8];
            float4 a1 = *(const float4*)&As[buf][k * GPA + ti * 8 + 4];
            ulonglong2 bA = *(const ulonglong2*)&Ws[buf][k * GBN + tj * 8];
            ulonglong2 bB = *(const ulonglong2*)&Ws[buf][k * GBN + tj * 8 + 4];
            float av[8] = {a0.x, a0.y, a0.z, a0.w, a1.x, a1.y, a1.z, a1.w};
#pragma unroll
            for (int i = 0; i < 8; i++) {
                unsigned long long ad = dup2(av[i]);
                ffma2(acc[i][0], ad, bA.x);
                ffma2(acc[i][1], ad, bA.y);
                ffma2(acc[i][2], ad, bB.x);
                ffma2(acc[i][3], ad, bB.y);
            }
        }
        if (more) {
            int nb = buf ^ 1;
#pragma unroll
            for (int p = 0; p < 2; p++) {
                As[nb][(ak4[p] * 4 + 0) * GPA + am[p]] = an[p].x;
                As[nb][(ak4[p] * 4 + 1) * GPA + am[p]] = an[p].y;
                As[nb][(ak4[p] * 4 + 2) * GPA + am[p]] = an[p].z;
                As[nb][(ak4[p] * 4 + 3) * GPA + am[p]] = an[p].w;
                *(float4*)&Ws[nb][wk[p] * GBN + wn4[p] * 4] = wn[p];
            }
            __syncthreads();
            buf = nb;
        }
    }

#pragma unroll
    for (int i = 0; i < 8; i++) {
        int gr = m0 + ti * 8 + i;
        float out[8];
#pragma unroll
        for (int j = 0; j < 4; j++) {
            float2 u = unpk2(acc[i][j]);
            out[2 * j] = u.x * scale;
            out[2 * j + 1] = u.y * scale;
        }
        float4* cp = (float4*)(C + (size_t)gr * Nc + n0 + tj * 8);
        cp[0] = make_float4(out[0], out[1], out[2], out[3]);
        cp[1] = make_float4(out[4], out[5], out[6], out[7]);
    }
}

// ---------------- fused flash attention with bias + mask ----------------
// CTA: (batch b = blockIdx.x, head h = blockIdx.y, i_tile = blockIdx.z), 256 threads.
// b is the FASTEST grid dim so the b=0/b=1 CTAs of the same (h, i-tile) get adjacent
// bids -> same wave, adjacent SMs, lockstep j-tile walk -> the second CTA's bias
// reads hit L2 (bias DRAM traffic ~halved; bias is the dominant DRAM stream).
// micro 4 rows x 8 cols; 128-row i-tiles; j-tiles of 64; online softmax;
// quad k-steps with LDS.128, outer unroll 1; bias staged through the idle Ps buffer.
#define SPITCH 68
#define ATT_IT 128
#define ATT_SMEM_FLOATS ((2 * ATT_IT + 2 * 64) * SPITCH + 64)

__global__ __launch_bounds__(256, 2) void attn_kernel(const float* __restrict__ qbuf,
                                                      const float* __restrict__ kvbuf,
                                                      const float* __restrict__ bias,
                                                      const float* __restrict__ maskf,
                                                      float* __restrict__ ao) {
    extern __shared__ float sm[];
    float* Qs = sm;                         // [128][68] q rows (i-major)
    float* Kt = Qs + ATT_IT * SPITCH;       // [64][68]  K transposed: Kt[d][j]
    float* Vs = Kt + 64 * SPITCH;           // [64][68]  V natural:    Vs[j][d]
    float* Ps = Vs + 64 * SPITCH;           // [128][68] bias tile, then probabilities [i][j]
    float* mk = Ps + ATT_IT * SPITCH;       // [64]      additive mask for this j tile

    int b = blockIdx.x, h = blockIdx.y;
    int i0g = blockIdx.z * ATT_IT;
    int tid = threadIdx.x;
    int ti = tid >> 3, tj = tid & 7;
    int ib = ti * 4;      // local row base (4 rows per thread, 0..124)
    int jc = tj * 8;      // local col base (8 cols per thread)

    // load Q tile once: 128 rows x 16 float4 = 2048 slots, 8 per thread
#pragma unroll
    for (int p = 0; p < 8; p++) {
        int idx = tid + p * 256;
        int r = idx >> 4, c4 = idx & 15;
        float4 v = *(const float4*)(qbuf + (size_t)(b * NSEQ + i0g + r) * DMODEL + h * DHD + c4 * 4);
        *(float4*)&Qs[r * SPITCH + c4 * 4] = v;
    }

    unsigned long long o2[4][4];
    float mrow[4], lrow[4];
#pragma unroll
    for (int ii = 0; ii < 4; ii++) {
        mrow[ii] = -INFINITY;
        lrow[ii] = 0.f;
#pragma unroll
        for (int dp = 0; dp < 4; dp++) o2[ii][dp] = 0ull;
    }

    const float* bias_tile = bias + ((size_t)h * NSEQ + i0g) * NSEQ;

    for (int jt = 0; jt < NSEQ / 64; jt++) {
        int j0g = jt * 64;
        __syncthreads();  // previous PV done (also covers initial Q staging)

        // stage K (transposed) and V: 64 rows x 16 float4, 4 iters/thread
#pragma unroll
        for (int p = 0; p < 4; p++) {
            int idx = tid + p * 256;
            int r = idx >> 4, c4 = idx & 15;
            const float* kvrow = kvbuf + (size_t)(b * NSEQ + j0g + r) * (2 * DHD);
            float4 k4 = *(const float4*)(kvrow + c4 * 4);
            Kt[(c4 * 4 + 0) * SPITCH + r] = k4.x;
            Kt[(c4 * 4 + 1) * SPITCH + r] = k4.y;
            Kt[(c4 * 4 + 2) * SPITCH + r] = k4.z;
            Kt[(c4 * 4 + 3) * SPITCH + r] = k4.w;
            float4 v4 = *(const float4*)(kvrow + DHD + c4 * 4);
            *(float4*)&Vs[r * SPITCH + c4 * 4] = v4;
        }
        // stage bias: 128 rows x 16 float4, 8 iters/thread (into Ps)
#pragma unroll
        for (int p = 0; p < 8; p++) {
            int idx = tid + p * 256;
            int r = idx >> 4, c4 = idx & 15;
            float4 b4 = *(const float4*)(bias_tile + (size_t)r * NSEQ + j0g + c4 * 4);
            *(float4*)&Ps[r * SPITCH + c4 * 4] = b4;
        }
        if (tid < 64) mk[tid] = maskf[b * NSEQ + j0g + tid];
        __syncthreads();

        // ---- S = Q @ K^T : quad k-steps, LDS.128, no outer unroll (reg cap) ----
        unsigned long long s2[4][4];
#pragma unroll
        for (int ii = 0; ii < 4; ii++)
#pragma unroll
            for (int jp = 0; jp < 4; jp++) s2[ii][jp] = 0ull;

#pragma unroll 1
        for (int dq = 0; dq < 16; dq++) {
            int dk = dq * 4;
            ulonglong2 kA[4], kB[4];
#pragma unroll
            for (int r = 0; r < 4; r++) {
                kA[r] = *(const ulonglong2*)&Kt[(dk + r) * SPITCH + jc];
                kB[r] = *(const ulonglong2*)&Kt[(dk + r) * SPITCH + jc + 4];
            }
#pragma unroll
            for (int ii = 0; ii < 4; ii++) {
                float4 q = *(const float4*)&Qs[(ib + ii) * SPITCH + dk];
                float qv[4] = {q.x, q.y, q.z, q.w};
#pragma unroll
                for (int r = 0; r < 4; r++) {
                    unsigned long long ad = dup2(qv[r]);
                    ffma2(s2[ii][0], ad, kA[r].x);
                    ffma2(s2[ii][1], ad, kA[r].y);
                    ffma2(s2[ii][2], ad, kB[r].x);
                    ffma2(s2[ii][3], ad, kB[r].y);
                }
            }
        }

        // ---- bias (from Ps smem) + additive mask + online softmax ----
        float4 mk0 = *(const float4*)&mk[jc];
        float4 mk1 = *(const float4*)&mk[jc + 4];
        float mkv[8] = {mk0.x, mk0.y, mk0.z, mk0.w, mk1.x, mk1.y, mk1.z, mk1.w};
#pragma unroll
        for (int ii = 0; ii < 4; ii++) {
            float4 bb0 = *(const float4*)&Ps[(ib + ii) * SPITCH + jc];
            float4 bb1 = *(const float4*)&Ps[(ib + ii) * SPITCH + jc + 4];
            float bvv[8] = {bb0.x, bb0.y, bb0.z, bb0.w, bb1.x, bb1.y, bb1.z, bb1.w};
            float sv[8];
#pragma unroll
            for (int jp = 0; jp < 4; jp++) {
                float2 u = unpk2(s2[ii][jp]);
                sv[2 * jp] = u.x;
                sv[2 * jp + 1] = u.y;
            }
#pragma unroll
            for (int jj = 0; jj < 8; jj++)
                sv[jj] = sv[jj] + bvv[jj] + mkv[jj];
            float tm = sv[0];
#pragma unroll
            for (int jj = 1; jj < 8; jj++) tm = fmaxf(tm, sv[jj]);
            tm = fmaxf(tm, __shfl_xor_sync(0xffffffffu, tm, 1));
            tm = fmaxf(tm, __shfl_xor_sync(0xffffffffu, tm, 2));
            tm = fmaxf(tm, __shfl_xor_sync(0xffffffffu, tm, 4));
            float mnew = fmaxf(mrow[ii], tm);
            float corr = __expf(mrow[ii] - mnew);
            float ps = 0.f;
#pragma unroll
            for (int jj = 0; jj < 8; jj++) {
                float p = __expf(sv[jj] - mnew);
                sv[jj] = p;
                ps += p;
            }
            ps += __shfl_xor_sync(0xffffffffu, ps, 1);
            ps += __shfl_xor_sync(0xffffffffu, ps, 2);
            ps += __shfl_xor_sync(0xffffffffu, ps, 4);
            lrow[ii] = lrow[ii] * corr + ps;
            mrow[ii] = mnew;
            unsigned long long cd = dup2(corr);
#pragma unroll
            for (int dp = 0; dp < 4; dp++) fmul2(o2[ii][dp], cd);
            *(float4*)&Ps[(ib + ii) * SPITCH + jc]     = make_float4(sv[0], sv[1], sv[2], sv[3]);
            *(float4*)&Ps[(ib + ii) * SPITCH + jc + 4] = make_float4(sv[4], sv[5], sv[6], sv[7]);
        }
        __syncthreads();

        // ---- O += P @ V : quad k-steps, LDS.128, no outer unroll (reg cap) ----
#pragma unroll 1
        for (int jq = 0; jq < 16; jq++) {
            int jk = jq * 4;
            ulonglong2 vA[4], vB[4];
#pragma unroll
            for (int r = 0; r < 4; r++) {
                vA[r] = *(const ulonglong2*)&Vs[(jk + r) * SPITCH + jc];
                vB[r] = *(const ulonglong2*)&Vs[(jk + r) * SPITCH + jc + 4];
            }
#pragma unroll
            for (int ii = 0; ii < 4; ii++) {
                float4 p4 = *(const float4*)&Ps[(ib + ii) * SPITCH + jk];
                float pv[4] = {p4.x, p4.y, p4.z, p4.w};
#pragma unroll
                for (int r = 0; r < 4; r++) {
                    unsigned long long ad = dup2(pv[r]);
                    ffma2(o2[ii][0], ad, vA[r].x);
                    ffma2(o2[ii][1], ad, vA[r].y);
                    ffma2(o2[ii][2], ad, vB[r].x);
                    ffma2(o2[ii][3], ad, vB[r].y);
                }
            }
        }
    }

    // epilogue: O / l -> ao[(b,i), h*64 + d]
#pragma unroll
    for (int ii = 0; ii < 4; ii++) {
        float rl = 1.f / lrow[ii];
        size_t base = (size_t)(b * NSEQ + i0g + ib + ii) * DMODEL + h * DHD + jc;
        float2 u0 = unpk2(o2[ii][0]);
        float2 u1 = unpk2(o2[ii][1]);
        float2 u2 = unpk2(o2[ii][2]);
        float2 u3 = unpk2(o2[ii][3]);
        *(float4*)(ao + base)     = make_float4(u0.x * rl, u0.y * rl, u1.x * rl, u1.y * rl);
        *(float4*)(ao + base + 4) = make_float4(u2.x * rl, u2.y * rl, u3.x * rl, u3.y * rl);
    }
}

// ---------------- launch ----------------
extern "C" void kernel_launch(void* const* d_in, const int* in_sizes, int n_in,
                              void* d_out, int out_size) {
    const float* x    = (const float*)d_in[0];
    const float* bias = (const float*)d_in[1];
    const float* lnw  = (const float*)d_in[2];
    const float* lnb  = (const float*)d_in[3];
    const float* wq   = (const float*)d_in[4];
    const float* wkv  = (const float*)d_in[5];
    const float* wo   = (const float*)d_in[6];
    const void*  mraw = d_in[7];
    float* out = (float*)d_out;

    float *p_xn, *p_q, *p_kv, *p_ao, *p_mask;
    cudaGetSymbolAddress((void**)&p_xn, g_xn);
    cudaGetSymbolAddress((void**)&p_q, g_q);
    cudaGetSymbolAddress((void**)&p_kv, g_kv);
    cudaGetSymbolAddress((void**)&p_ao, g_ao);
    cudaGetSymbolAddress((void**)&p_mask, g_mask);

    const int attn_smem = ATT_SMEM_FLOATS * (int)sizeof(float);
    cudaFuncSetAttribute(attn_kernel, cudaFuncAttributeMaxDynamicSharedMemorySize, attn_smem);

    // LN rows + folded mask normalization (overflow blocks)
    ln_kernel<<<LN_ROWS + MASK_BLOCKS, 256>>>(x, lnw, lnb, p_xn, mraw, p_mask);
    // fused: blocks 0..7 per m-tile -> q = xn @ wq * 0.125 ; block 8 -> kv = x @ wkv
    // grid (9, 32) = 288 CTAs, 2/SM -> single wave on 148 SMs
    sgemm_kernel<<<dim3(9, 32), 256>>>(p_xn, wq, p_q, DMODEL, DMODEL, 0.125f,
                                       x, wkv, p_kv, 2 * DHD, 1.f, 8);
    // attention: b fastest grid dim -> batch-pair bias L2 reuse; 512 CTAs, 2 waves
    attn_kernel<<<dim3(NB, NH, NSEQ / ATT_IT), 256, attn_smem>>>(p_q, p_kv, bias, p_mask, p_ao);
    // out = ao @ wo  (M=4096, Nc=1024, K=1024): primary set only (split beyond grid)
    sgemm_kernel<<<dim3(8, 32), 256>>>(p_ao, wo, out, DMODEL, DMODEL, 1.f,
                                       p_ao, wo, out, DMODEL, 1.f, 1000);
}

// round 11
// speedup vs baseline: 1.0007x; 1.0007x over previous
#include <cuda_runtime.h>
#include <math.h>
#include <float.h>

#define NB     2
#define NSEQ   2048
#define DMODEL 1024
#define NH     16
#define DHD    64

// ---------------- scratch (device globals; no allocations allowed) ----------------
__device__ float g_xn  [NB * NSEQ * DMODEL];   // layernormed x
__device__ float g_q   [NB * NSEQ * DMODEL];   // q (scaled), layout [b*N + i][h*64 + d]
__device__ float g_kv  [NB * NSEQ * 2 * DHD];  // kv, layout [b*N + j][0:64 k | 64:128 v]
__device__ float g_ao  [NB * NSEQ * DMODEL];   // attention output, [b*N + i][h*64 + d]
__device__ float g_mask[NB * NSEQ];            // additive mask: 0 (keep) / -3e38 (drop)

// ---------------- packed f32x2 helpers (Blackwell FFMA2) ----------------
__device__ __forceinline__ unsigned long long dup2(float x) {
    unsigned long long r;
    unsigned int u = __float_as_uint(x);
    asm("mov.b64 %0, {%1, %2};" : "=l"(r) : "r"(u), "r"(u));
    return r;
}
__device__ __forceinline__ float2 unpk2(unsigned long long v) {
    unsigned int lo, hi;
    asm("mov.b64 {%0, %1}, %2;" : "=r"(lo), "=r"(hi) : "l"(v));
    return make_float2(__uint_as_float(lo), __uint_as_float(hi));
}
__device__ __forceinline__ void ffma2(unsigned long long& d, unsigned long long a, unsigned long long b) {
    asm("fma.rn.f32x2 %0, %1, %2, %0;" : "+l"(d) : "l"(a), "l"(b));
}
__device__ __forceinline__ void fmul2(unsigned long long& d, unsigned long long a) {
    asm("mul.rn.f32x2 %0, %0, %1;" : "+l"(d) : "l"(a));
}

// ---------------- layernorm (+ folded mask normalization on overflow blocks) ----------------
#define LN_ROWS (NB * NSEQ)
#define MASK_BLOCKS 8

__global__ __launch_bounds__(256) void ln_kernel(const float* __restrict__ x,
                                                 const float* __restrict__ w,
                                                 const float* __restrict__ bb,
                                                 float* __restrict__ xn,
                                                 const void* __restrict__ mraw,
                                                 float* __restrict__ mout) {
    int row = blockIdx.x;
    int t = threadIdx.x;
    if (row >= LN_ROWS) {
        // ---- mask path ----
        __shared__ int s_mode;
        if (t == 0) {
            const unsigned int* u = (const unsigned int*)mraw;
            bool isI = true, isF = true;
            for (int i = 0; i < 1024; i++) {       // first 4096 bytes, valid for any candidate dtype
                unsigned int v = u[i];
                if (v > 1u) isI = false;
                if (v != 0u && v != 0x3F800000u) isF = false;
            }
            s_mode = isI ? 1 : (isF ? 2 : 0);
        }
        __syncthreads();
        int mode = s_mode;
        int mb = row - LN_ROWS;
        for (int i = mb * 256 + t; i < LN_ROWS; i += MASK_BLOCKS * 256) {
            bool keep;
            if (mode == 1)      keep = (((const int*)mraw)[i]   != 0);
            else if (mode == 2) keep = (((const float*)mraw)[i] != 0.f);
            else                keep = (((const unsigned char*)mraw)[i] != 0);
            mout[i] = keep ? 0.f : -3.0e38f;
        }
        return;
    }
    const float4* xr = (const float4*)(x + (size_t)row * DMODEL);
    float4 v = xr[t];
    float s = v.x + v.y + v.z + v.w;
    float q = v.x * v.x + v.y * v.y + v.z * v.z + v.w * v.w;
#pragma unroll
    for (int o = 16; o > 0; o >>= 1) {
        s += __shfl_xor_sync(0xffffffffu, s, o);
        q += __shfl_xor_sync(0xffffffffu, q, o);
    }
    __shared__ float ss[8], sq[8];
    int wid = t >> 5, lid = t & 31;
    if (lid == 0) { ss[wid] = s; sq[wid] = q; }
    __syncthreads();
    s = 0.f; q = 0.f;
#pragma unroll
    for (int i = 0; i < 8; i++) { s += ss[i]; q += sq[i]; }
    float mu = s * (1.f / DMODEL);
    float var = q * (1.f / DMODEL) - mu * mu;
    float rstd = rsqrtf(var + 1e-5f);
    float4 wv = ((const float4*)w)[t];
    float4 bv = ((const float4*)bb)[t];
    float4 o;
    o.x = (v.x - mu) * rstd * wv.x + bv.x;
    o.y = (v.y - mu) * rstd * wv.y + bv.y;
    o.z = (v.z - mu) * rstd * wv.z + bv.z;
    o.w = (v.w - mu) * rstd * wv.w + bv.w;
    ((float4*)(xn + (size_t)row * DMODEL))[t] = o;
}

// ---------------- SGEMM 128x128: C = scale * (A[M,K] @ W[K,Nc]) ----------------
// (unchanged from the verified R10 baseline: measured 201us, fma=53%, occ=2 CTA/SM)
#define GBM 128
#define GBN 128
#define GBK 16
#define GPA 132

__global__ __launch_bounds__(256, 2) void sgemm_kernel(const float* __restrict__ Ap,
                                                       const float* __restrict__ Wp,
                                                       float* __restrict__ Cp,
                                                       int Ncp, int K, float scalep,
                                                       const float* __restrict__ A2,
                                                       const float* __restrict__ W2,
                                                       float* __restrict__ C2,
                                                       int Nc2, float scale2, int split) {
    __shared__ float As[2][GBK * GPA];
    __shared__ float Ws[2][GBK * GBN];
    int tid = threadIdx.x;
    int ti = tid >> 4, tj = tid & 15;

    const float* A; const float* W; float* C;
    int Nc; float scale; int n0;
    if ((int)blockIdx.x >= split) {
        A = A2; W = W2; C = C2; Nc = Nc2; scale = scale2; n0 = 0;
    } else {
        A = Ap; W = Wp; C = Cp; Nc = Ncp; scale = scalep; n0 = blockIdx.x * GBN;
    }
    int m0 = blockIdx.y * GBM;

    int am[2], ak4[2], wk[2], wn4[2];
#pragma unroll
    for (int p = 0; p < 2; p++) {
        int idx = tid + p * 256;
        am[p]  = idx >> 2;  ak4[p] = idx & 3;
        wk[p]  = idx >> 5;  wn4[p] = idx & 31;
    }

    unsigned long long acc[8][4];
#pragma unroll
    for (int i = 0; i < 8; i++)
#pragma unroll
        for (int j = 0; j < 4; j++) acc[i][j] = 0ull;

#pragma unroll
    for (int p = 0; p < 2; p++) {
        float4 av = *(const float4*)(A + (size_t)(m0 + am[p]) * K + ak4[p] * 4);
        As[0][(ak4[p] * 4 + 0) * GPA + am[p]] = av.x;
        As[0][(ak4[p] * 4 + 1) * GPA + am[p]] = av.y;
        As[0][(ak4[p] * 4 + 2) * GPA + am[p]] = av.z;
        As[0][(ak4[p] * 4 + 3) * GPA + am[p]] = av.w;
        float4 wv = *(const float4*)(W + (size_t)wk[p] * Nc + n0 + wn4[p] * 4);
        *(float4*)&Ws[0][wk[p] * GBN + wn4[p] * 4] = wv;
    }
    __syncthreads();

    int buf = 0;
    for (int kb = 0; kb < K; kb += GBK) {
        float4 an[2], wn[2];
        bool more = (kb + GBK) < K;
        if (more) {
#pragma unroll
            for (int p = 0; p < 2; p++) {
                an[p] = *(const float4*)(A + (size_t)(m0 + am[p]) * K + kb + GBK + ak4[p] * 4);
                wn[p] = *(const float4*)(W + (size_t)(kb + GBK + wk[p]) * Nc + n0 + wn4[p] * 4);
            }
        }
#pragma unroll
        for (int k = 0; k < GBK; k++) {
            float4 a0 = *(const float4*)&As[buf][k * GPA + ti * 8];
            float4 a1 = *(const float4*)&As[buf][k * GPA + ti * 8 + 4];
            ulonglong2 bA = *(const ulonglong2*)&Ws[buf][k * GBN + tj * 8];
            ulonglong2 bB = *(const ulonglong2*)&Ws[buf][k * GBN + tj * 8 + 4];
            float av[8] = {a0.x, a0.y, a0.z, a0.w, a1.x, a1.y, a1.z, a1.w};
#pragma unroll
            for (int i = 0; i < 8; i++) {
                unsigned long long ad = dup2(av[i]);
                ffma2(acc[i][0], ad, bA.x);
                ffma2(acc[i][1], ad, bA.y);
                ffma2(acc[i][2], ad, bB.x);
                ffma2(acc[i][3], ad, bB.y);
            }
        }
        if (more) {
            int nb = buf ^ 1;
#pragma unroll
            for (int p = 0; p < 2; p++) {
                As[nb][(ak4[p] * 4 + 0) * GPA + am[p]] = an[p].x;
                As[nb][(ak4[p] * 4 + 1) * GPA + am[p]] = an[p].y;
                As[nb][(ak4[p] * 4 + 2) * GPA + am[p]] = an[p].z;
                As[nb][(ak4[p] * 4 + 3) * GPA + am[p]] = an[p].w;
                *(float4*)&Ws[nb][wk[p] * GBN + wn4[p] * 4] = wn[p];
            }
            __syncthreads();
            buf = nb;
        }
    }

#pragma unroll
    for (int i = 0; i < 8; i++) {
        int gr = m0 + ti * 8 + i;
        float out[8];
#pragma unroll
        for (int j = 0; j < 4; j++) {
            float2 u = unpk2(acc[i][j]);
            out[2 * j] = u.x * scale;
            out[2 * j + 1] = u.y * scale;
        }
        float4* cp = (float4*)(C + (size_t)gr * Nc + n0 + tj * 8);
        cp[0] = make_float4(out[0], out[1], out[2], out[3]);
        cp[1] = make_float4(out[4], out[5], out[6], out[7]);
    }
}

// ---------------- fused flash attention with bias + mask ----------------
// CTA: (batch b, head h, i_tile), 256 threads, micro 4x8, 128-row i-tiles,
// b fastest grid dim for batch-pair bias L2 reuse. REG-PRESSURE FIX vs R10:
// QK/PV inner loops immediate-consume K/V row pairs (live K/V regs 4 instead of
// 32) with Q/P fragments (16 regs) held per quad -> peak live ~105 < 128 cap,
// eliminating the suspected inner-loop spills behind attn at ~38% of fma roof.
// Mask folded into bias during staging (drops mk buffer + 8 regs + 32 FADD/jt).
#define SPITCH 68
#define ATT_IT 128
#define ATT_SMEM_FLOATS ((2 * ATT_IT + 2 * 64) * SPITCH)

__global__ __launch_bounds__(256, 2) void attn_kernel(const float* __restrict__ qbuf,
                                                      const float* __restrict__ kvbuf,
                                                      const float* __restrict__ bias,
                                                      const float* __restrict__ maskf,
                                                      float* __restrict__ ao) {
    extern __shared__ float sm[];
    float* Qs = sm;                         // [128][68] q rows (i-major)
    float* Kt = Qs + ATT_IT * SPITCH;       // [64][68]  K transposed: Kt[d][j]
    float* Vs = Kt + 64 * SPITCH;           // [64][68]  V natural:    Vs[j][d]
    float* Ps = Vs + 64 * SPITCH;           // [128][68] bias+mask tile, then probs [i][j]

    int b = blockIdx.x, h = blockIdx.y;
    int i0g = blockIdx.z * ATT_IT;
    int tid = threadIdx.x;
    int ti = tid >> 3, tj = tid & 7;
    int ib = ti * 4;      // local row base (4 rows per thread, 0..124)
    int jc = tj * 8;      // local col base (8 cols per thread)

    // load Q tile once: 128 rows x 16 float4 = 2048 slots, 8 per thread
#pragma unroll
    for (int p = 0; p < 8; p++) {
        int idx = tid + p * 256;
        int r = idx >> 4, c4 = idx & 15;
        float4 v = *(const float4*)(qbuf + (size_t)(b * NSEQ + i0g + r) * DMODEL + h * DHD + c4 * 4);
        *(float4*)&Qs[r * SPITCH + c4 * 4] = v;
    }

    unsigned long long o2[4][4];
    float mrow[4], lrow[4];
#pragma unroll
    for (int ii = 0; ii < 4; ii++) {
        mrow[ii] = -INFINITY;
        lrow[ii] = 0.f;
#pragma unroll
        for (int dp = 0; dp < 4; dp++) o2[ii][dp] = 0ull;
    }

    const float* bias_tile = bias + ((size_t)h * NSEQ + i0g) * NSEQ;
    const float* mask_b = maskf + b * NSEQ;

    for (int jt = 0; jt < NSEQ / 64; jt++) {
        int j0g = jt * 64;
        __syncthreads();  // previous PV done (also covers initial Q staging)

        // stage K (transposed) and V: 64 rows x 16 float4, 4 iters/thread
#pragma unroll
        for (int p = 0; p < 4; p++) {
            int idx = tid + p * 256;
            int r = idx >> 4, c4 = idx & 15;
            const float* kvrow = kvbuf + (size_t)(b * NSEQ + j0g + r) * (2 * DHD);
            float4 k4 = *(const float4*)(kvrow + c4 * 4);
            Kt[(c4 * 4 + 0) * SPITCH + r] = k4.x;
            Kt[(c4 * 4 + 1) * SPITCH + r] = k4.y;
            Kt[(c4 * 4 + 2) * SPITCH + r] = k4.z;
            Kt[(c4 * 4 + 3) * SPITCH + r] = k4.w;
            float4 v4 = *(const float4*)(kvrow + DHD + c4 * 4);
            *(float4*)&Vs[r * SPITCH + c4 * 4] = v4;
        }
        // stage bias + additive mask: 128 rows x 16 float4, 8 iters/thread (into Ps)
#pragma unroll
        for (int p = 0; p < 8; p++) {
            int idx = tid + p * 256;
            int r = idx >> 4, c4 = idx & 15;
            float4 b4 = *(const float4*)(bias_tile + (size_t)r * NSEQ + j0g + c4 * 4);
            float4 m4 = *(const float4*)(mask_b + j0g + c4 * 4);
            b4.x += m4.x; b4.y += m4.y; b4.z += m4.z; b4.w += m4.w;
            *(float4*)&Ps[r * SPITCH + c4 * 4] = b4;
        }
        __syncthreads();

        // ---- S = Q @ K^T : quad k-steps; K rows immediate-consumed (4 live regs) ----
        unsigned long long s2[4][4];
#pragma unroll
        for (int ii = 0; ii < 4; ii++)
#pragma unroll
            for (int jp = 0; jp < 4; jp++) s2[ii][jp] = 0ull;

#pragma unroll 1
        for (int dq = 0; dq < 16; dq++) {
            int dk = dq * 4;
            float4 qf[4];
#pragma unroll
            for (int ii = 0; ii < 4; ii++)
                qf[ii] = *(const float4*)&Qs[(ib + ii) * SPITCH + dk];
#pragma unroll
            for (int r = 0; r < 4; r++) {
                ulonglong2 kA = *(const ulonglong2*)&Kt[(dk + r) * SPITCH + jc];
                ulonglong2 kB = *(const ulonglong2*)&Kt[(dk + r) * SPITCH + jc + 4];
#pragma unroll
                for (int ii = 0; ii < 4; ii++) {
                    float qv = (r == 0) ? qf[ii].x : (r == 1) ? qf[ii].y
                             : (r == 2) ? qf[ii].z : qf[ii].w;
                    unsigned long long ad = dup2(qv);
                    ffma2(s2[ii][0], ad, kA.x);
                    ffma2(s2[ii][1], ad, kA.y);
                    ffma2(s2[ii][2], ad, kB.x);
                    ffma2(s2[ii][3], ad, kB.y);
                }
            }
        }

        // ---- bias+mask (from Ps smem) + online softmax ----
#pragma unroll
        for (int ii = 0; ii < 4; ii++) {
            float4 bb0 = *(const float4*)&Ps[(ib + ii) * SPITCH + jc];
            float4 bb1 = *(const float4*)&Ps[(ib + ii) * SPITCH + jc + 4];
            float bvv[8] = {bb0.x, bb0.y, bb0.z, bb0.w, bb1.x, bb1.y, bb1.z, bb1.w};
            float sv[8];
#pragma unroll
            for (int jp = 0; jp < 4; jp++) {
                float2 u = unpk2(s2[ii][jp]);
                sv[2 * jp] = u.x;
                sv[2 * jp + 1] = u.y;
            }
#pragma unroll
            for (int jj = 0; jj < 8; jj++)
                sv[jj] = sv[jj] + bvv[jj];
            float tm = sv[0];
#pragma unroll
            for (int jj = 1; jj < 8; jj++) tm = fmaxf(tm, sv[jj]);
            tm = fmaxf(tm, __shfl_xor_sync(0xffffffffu, tm, 1));
            tm = fmaxf(tm, __shfl_xor_sync(0xffffffffu, tm, 2));
            tm = fmaxf(tm, __shfl_xor_sync(0xffffffffu, tm, 4));
            float mnew = fmaxf(mrow[ii], tm);
            float corr = __expf(mrow[ii] - mnew);
            float ps = 0.f;
#pragma unroll
            for (int jj = 0; jj < 8; jj++) {
                float p = __expf(sv[jj] - mnew);
                sv[jj] = p;
                ps += p;
            }
            ps += __shfl_xor_sync(0xffffffffu, ps, 1);
            ps += __shfl_xor_sync(0xffffffffu, ps, 2);
            ps += __shfl_xor_sync(0xffffffffu, ps, 4);
            lrow[ii] = lrow[ii] * corr + ps;
            mrow[ii] = mnew;
            unsigned long long cd = dup2(corr);
#pragma unroll
            for (int dp = 0; dp < 4; dp++) fmul2(o2[ii][dp], cd);
            *(float4*)&Ps[(ib + ii) * SPITCH + jc]     = make_float4(sv[0], sv[1], sv[2], sv[3]);
            *(float4*)&Ps[(ib + ii) * SPITCH + jc + 4] = make_float4(sv[4], sv[5], sv[6], sv[7]);
        }
        __syncthreads();

        // ---- O += P @ V : quad k-steps; V rows immediate-consumed (4 live regs) ----
#pragma unroll 1
        for (int jq = 0; jq < 16; jq++) {
            int jk = jq * 4;
            float4 pf[4];
#pragma unroll
            for (int ii = 0; ii < 4; ii++)
                pf[ii] = *(const float4*)&Ps[(ib + ii) * SPITCH + jk];
#pragma unroll
            for (int r = 0; r < 4; r++) {
                ulonglong2 vA = *(const ulonglong2*)&Vs[(jk + r) * SPITCH + jc];
                ulonglong2 vB = *(const ulonglong2*)&Vs[(jk + r) * SPITCH + jc + 4];
#pragma unroll
                for (int ii = 0; ii < 4; ii++) {
                    float pv = (r == 0) ? pf[ii].x : (r == 1) ? pf[ii].y
                             : (r == 2) ? pf[ii].z : pf[ii].w;
                    unsigned long long ad = dup2(pv);
                    ffma2(o2[ii][0], ad, vA.x);
                    ffma2(o2[ii][1], ad, vA.y);
                    ffma2(o2[ii][2], ad, vB.x);
                    ffma2(o2[ii][3], ad, vB.y);
                }
            }
        }
    }

    // epilogue: O / l -> ao[(b,i), h*64 + d]
#pragma unroll
    for (int ii = 0; ii < 4; ii++) {
        float rl = 1.f / lrow[ii];
        size_t base = (size_t)(b * NSEQ + i0g + ib + ii) * DMODEL + h * DHD + jc;
        float2 u0 = unpk2(o2[ii][0]);
        float2 u1 = unpk2(o2[ii][1]);
        float2 u2 = unpk2(o2[ii][2]);
        float2 u3 = unpk2(o2[ii][3]);
        *(float4*)(ao + base)     = make_float4(u0.x * rl, u0.y * rl, u1.x * rl, u1.y * rl);
        *(float4*)(ao + base + 4) = make_float4(u2.x * rl, u2.y * rl, u3.x * rl, u3.y * rl);
    }
}

// ---------------- launch ----------------
extern "C" void kernel_launch(void* const* d_in, const int* in_sizes, int n_in,
                              void* d_out, int out_size) {
    const float* x    = (const float*)d_in[0];
    const float* bias = (const float*)d_in[1];
    const float* lnw  = (const float*)d_in[2];
    const float* lnb  = (const float*)d_in[3];
    const float* wq   = (const float*)d_in[4];
    const float* wkv  = (const float*)d_in[5];
    const float* wo   = (const float*)d_in[6];
    const void*  mraw = d_in[7];
    float* out = (float*)d_out;

    float *p_xn, *p_q, *p_kv, *p_ao, *p_mask;
    cudaGetSymbolAddress((void**)&p_xn, g_xn);
    cudaGetSymbolAddress((void**)&p_q, g_q);
    cudaGetSymbolAddress((void**)&p_kv, g_kv);
    cudaGetSymbolAddress((void**)&p_ao, g_ao);
    cudaGetSymbolAddress((void**)&p_mask, g_mask);

    const int attn_smem = ATT_SMEM_FLOATS * (int)sizeof(float);
    cudaFuncSetAttribute(attn_kernel, cudaFuncAttributeMaxDynamicSharedMemorySize, attn_smem);

    // LN rows + folded mask normalization (overflow blocks)
    ln_kernel<<<LN_ROWS + MASK_BLOCKS, 256>>>(x, lnw, lnb, p_xn, mraw, p_mask);
    // fused: blocks 0..7 per m-tile -> q = xn @ wq * 0.125 ; block 8 -> kv = x @ wkv
    sgemm_kernel<<<dim3(9, 32), 256>>>(p_xn, wq, p_q, DMODEL, DMODEL, 0.125f,
                                       x, wkv, p_kv, 2 * DHD, 1.f, 8);
    // attention: b fastest grid dim -> batch-pair bias L2 reuse; 512 CTAs, 2 waves
    attn_kernel<<<dim3(NB, NH, NSEQ / ATT_IT), 256, attn_smem>>>(p_q, p_kv, bias, p_mask, p_ao);
    // out = ao @ wo  (M=4096, Nc=1024, K=1024): primary set only (split beyond grid)
    sgemm_kernel<<<dim3(8, 32), 256>>>(p_ao, wo, out, DMODEL, DMODEL, 1.f,
                                       p_ao, wo, out, DMODEL, 1.f, 1000);
}